// round 1
// baseline (speedup 1.0000x reference)
#include <cuda_runtime.h>
#include <cstdint>
#include <cstddef>

// out = x @ Wv^T + bv.  (softmax rows sum to 1, so the reference's
// einsum('btu,btj->btj', softmax_weights, v) == v exactly up to fp rounding.)
//
// GEMM: M=8192 (B*T), K=1024, N=64, fp32 via packed fma.rn.f32x2.
// Split-K=4 with fp32 partials in __device__ scratch + reduce kernel.

typedef unsigned long long ull;

#define M_TOTAL 8192
#define NEMB    1024
#define NH      64
#define SPLITK  4
#define KSPLIT  (NEMB / SPLITK)   // 256
#define BM      128
#define BK      16
#define BKP     20                // padded pitch: conflict-free LDS.64, 16B-aligned rows
#define NCHUNK  (KSPLIT / BK)     // 16
#define THREADS 128

__device__ float g_part[SPLITK * M_TOTAL * NH];   // 8 MB scratch (fits L2)

__device__ __forceinline__ void cp_async16(uint32_t s, const void* g) {
    asm volatile("cp.async.cg.shared.global [%0], [%1], 16;" :: "r"(s), "l"(g));
}

__global__ __launch_bounds__(THREADS) void vproj_kernel(
    const float* __restrict__ x, const float* __restrict__ W)
{
    __shared__ float xs[2][BM][BKP];
    __shared__ float ws[2][NH][BKP];

    const int t       = threadIdx.x;
    const int rowbase = blockIdx.x * BM;
    const int kbase   = blockIdx.y * KSPLIT;
    const int tr      = t >> 3;     // 0..15  (rows: tr + 16*i)
    const int tc      = t & 7;      // 0..7   (cols: tc + 8*j)

    const uint32_t xs_s = (uint32_t)__cvta_generic_to_shared(&xs[0][0][0]);
    const uint32_t ws_s = (uint32_t)__cvta_generic_to_shared(&ws[0][0][0]);

    // acc[i][j] packs {sum over even k, sum over odd k} for output (row i, col j)
    ull acc[8][8];
#pragma unroll
    for (int i = 0; i < 8; i++)
#pragma unroll
        for (int j = 0; j < 8; j++) acc[i][j] = 0ull;

    // ---- prefetch chunk 0 into buffer 0 ----
    {
        const int k0 = kbase;
#pragma unroll
        for (int i = 0; i < 4; i++) {
            int id = t + THREADS * i; int r = id >> 2, sg = id & 3;
            cp_async16(xs_s + (uint32_t)(((0 * BM + r) * BKP + sg * 4) * 4),
                       x + (size_t)(rowbase + r) * NEMB + k0 + sg * 4);
        }
#pragma unroll
        for (int i = 0; i < 2; i++) {
            int id = t + THREADS * i; int r = id >> 2, sg = id & 3;
            cp_async16(ws_s + (uint32_t)(((0 * NH + r) * BKP + sg * 4) * 4),
                       W + (size_t)r * NEMB + k0 + sg * 4);
        }
        asm volatile("cp.async.commit_group;");
    }

#pragma unroll 1
    for (int c = 0; c < NCHUNK; c++) {
        const int cur = c & 1;
        if (c + 1 < NCHUNK) {
            const int nb = cur ^ 1;
            const int k0 = kbase + (c + 1) * BK;
#pragma unroll
            for (int i = 0; i < 4; i++) {
                int id = t + THREADS * i; int r = id >> 2, sg = id & 3;
                cp_async16(xs_s + (uint32_t)(((nb * BM + r) * BKP + sg * 4) * 4),
                           x + (size_t)(rowbase + r) * NEMB + k0 + sg * 4);
            }
#pragma unroll
            for (int i = 0; i < 2; i++) {
                int id = t + THREADS * i; int r = id >> 2, sg = id & 3;
                cp_async16(ws_s + (uint32_t)(((nb * NH + r) * BKP + sg * 4) * 4),
                           W + (size_t)r * NEMB + k0 + sg * 4);
            }
            asm volatile("cp.async.commit_group;");
            asm volatile("cp.async.wait_group 1;");
        } else {
            asm volatile("cp.async.wait_group 0;");
        }
        __syncthreads();

        // ---- compute on buffer `cur`: 8x8 register tile, k in even/odd pairs ----
#pragma unroll
        for (int kk = 0; kk < BK; kk += 2) {
            ull xv[8], wv[8];
#pragma unroll
            for (int i = 0; i < 8; i++)
                xv[i] = *(const ull*)&xs[cur][tr + 16 * i][kk];
#pragma unroll
            for (int j = 0; j < 8; j++)
                wv[j] = *(const ull*)&ws[cur][tc + 8 * j][kk];
#pragma unroll
            for (int i = 0; i < 8; i++)
#pragma unroll
                for (int j = 0; j < 8; j++)
                    asm("fma.rn.f32x2 %0, %1, %2, %0;"
                        : "+l"(acc[i][j]) : "l"(xv[i]), "l"(wv[j]));
        }
        __syncthreads();
    }

    // ---- epilogue: fold even/odd halves, write split partial ----
    float* op = g_part + (size_t)blockIdx.y * (M_TOTAL * NH);
#pragma unroll
    for (int i = 0; i < 8; i++) {
        const int row = rowbase + tr + 16 * i;
#pragma unroll
        for (int j = 0; j < 8; j++) {
            float lo, hi;
            asm("mov.b64 {%0, %1}, %2;" : "=f"(lo), "=f"(hi) : "l"(acc[i][j]));
            op[(size_t)row * NH + tc + 8 * j] = lo + hi;
        }
    }
}

__global__ void reduce_kernel(const float* __restrict__ bv, float* __restrict__ out)
{
    const int tid = blockIdx.x * blockDim.x + threadIdx.x;   // 131072 threads
    const int S4  = (M_TOTAL * NH) / 4;
    const float4* p = reinterpret_cast<const float4*>(g_part);
    float4 a = p[tid];
    float4 b = p[tid + S4];
    float4 c = p[tid + 2 * S4];
    float4 d = p[tid + 3 * S4];
    float4 bb = reinterpret_cast<const float4*>(bv)[tid & 15];  // (4*tid)%64 / 4
    float4 o;
    o.x = a.x + b.x + c.x + d.x + bb.x;
    o.y = a.y + b.y + c.y + d.y + bb.y;
    o.z = a.z + b.z + c.z + d.z + bb.z;
    o.w = a.w + b.w + c.w + d.w + bb.w;
    reinterpret_cast<float4*>(out)[tid] = o;
}

extern "C" void kernel_launch(void* const* d_in, const int* in_sizes, int n_in,
                              void* d_out, int out_size)
{
    const float* x  = (const float*)d_in[0];
    const float* Wv = (const float*)d_in[5];
    const float* bv = (const float*)d_in[6];

    dim3 grid(M_TOTAL / BM, SPLITK);                 // 64 x 4 = 256 CTAs
    vproj_kernel<<<grid, THREADS>>>(x, Wv);
    reduce_kernel<<<(M_TOTAL * NH / 4) / 256, 256>>>(bv, (float*)d_out);
}

// round 3
// speedup vs baseline: 1.4917x; 1.4917x over previous
#include <cuda_runtime.h>
#include <cuda_bf16.h>
#include <cstdint>
#include <cstddef>

// out = x @ Wv^T + bv.  (Reference's softmax rows sum to 1, so its final
// einsum('btu,btj->btj', weights, v) == v + rounding; Q/K/softmax are dead.)
//
// fp32 GEMM M=8192, K=1024, N=64 via bf16-split on PORTABLE mma.sync
// (tcgen05 PTX is compute_103a-only; this harness compiles via compute_103):
//   x = xh + xl, W = wh + wl (bf16); D += xh*wh + xh*wl + xl*wh (fp32 acc).
// 128 CTAs x 128 threads; CTA = 64 M-rows; warp = 16 rows x 64 cols.
// K chunks of 32, LDG->split->STS pipeline double-buffered, 1 sync/chunk.

#define NEMB    1024
#define NH      64
#define MT      64              // M rows per CTA
#define KC      32              // K per chunk
#define NCHUNK  (NEMB / KC)     // 32
#define THREADS 128
#define GRID    128             // 8192 / 64
#define PITCH   80              // bytes per row of 32 bf16 (40 bf16, conflict-free)
#define TILE_B  (64 * PITCH)    // 5120 bytes per tile (x tiles: 64 rows; w tiles: 64 n)

__shared__ __align__(16) unsigned char smbuf[2][4][TILE_B]; // {xh, xl, wh, wl}
__shared__ float bias_s[NH];

__device__ __forceinline__ void split4(float4 f, uint32_t& uh0, uint32_t& uh1,
                                       uint32_t& ul0, uint32_t& ul1) {
    // pack k-ascending: low 16 bits = lower k
    asm("cvt.rn.bf16x2.f32 %0, %1, %2;" : "=r"(uh0) : "f"(f.y), "f"(f.x));
    asm("cvt.rn.bf16x2.f32 %0, %1, %2;" : "=r"(uh1) : "f"(f.w), "f"(f.z));
    float r0 = f.x - __uint_as_float(uh0 << 16);
    float r1 = f.y - __uint_as_float(uh0 & 0xffff0000u);
    float r2 = f.z - __uint_as_float(uh1 << 16);
    float r3 = f.w - __uint_as_float(uh1 & 0xffff0000u);
    asm("cvt.rn.bf16x2.f32 %0, %1, %2;" : "=r"(ul0) : "f"(r1), "f"(r0));
    asm("cvt.rn.bf16x2.f32 %0, %1, %2;" : "=r"(ul1) : "f"(r3), "f"(r2));
}

__device__ __forceinline__ void mma16816(float& c0, float& c1, float& c2, float& c3,
                                         uint32_t a0, uint32_t a1, uint32_t a2, uint32_t a3,
                                         uint32_t b0, uint32_t b1) {
    asm volatile(
        "mma.sync.aligned.m16n8k16.row.col.f32.bf16.bf16.f32 "
        "{%0,%1,%2,%3}, {%4,%5,%6,%7}, {%8,%9}, {%0,%1,%2,%3};"
        : "+f"(c0), "+f"(c1), "+f"(c2), "+f"(c3)
        : "r"(a0), "r"(a1), "r"(a2), "r"(a3), "r"(b0), "r"(b1));
}

__device__ __forceinline__ uint32_t lds32(const unsigned char* p) {
    uint32_t v;
    asm volatile("ld.shared.b32 %0, [%1];" : "=r"(v) : "l"(p));
    return v;
}

__global__ void __launch_bounds__(THREADS)
vproj(const float* __restrict__ x, const float* __restrict__ W,
      const float* __restrict__ bv, float* __restrict__ out)
{
    const int t   = threadIdx.x;
    const int wid = t >> 5;
    const int lid = t & 31;
    const int rowbase = blockIdx.x * MT;

    if (t < 16) ((float4*)bias_s)[t] = ((const float4*)bv)[t];

    // per-thread load slots: idx = t + 128*i, row = idx>>3, q = idx&7 (float4 in row)
    const int lr = t >> 3;          // base row for i=0 (rows advance by 16 per i)
    const int lq = t & 7;

    float acc[8][4];
#pragma unroll
    for (int j = 0; j < 8; j++)
#pragma unroll
        for (int e = 0; e < 4; e++) acc[j][e] = 0.0f;

    float4 xr[4], wr[4];
    // prefetch chunk 0
#pragma unroll
    for (int i = 0; i < 4; i++) {
        xr[i] = *(const float4*)(x + (size_t)(rowbase + lr + 16 * i) * NEMB + lq * 4);
        wr[i] = *(const float4*)(W + (size_t)(lr + 16 * i) * NEMB + lq * 4);
    }

    // per-lane fragment addresses (byte offsets within a tile)
    const int frow = (wid << 4) + (lid >> 2);     // A row for this lane
    const int fcol = (lid & 3) << 2;              // byte offset of k-pair
    const int aoff = frow * PITCH + fcol;
    const int boff_base = (lid >> 2) * PITCH + fcol;

#pragma unroll 1
    for (int c = 0; c < NCHUNK; c++) {
        const int buf = c & 1;
        unsigned char* xh = smbuf[buf][0];
        unsigned char* xl = smbuf[buf][1];
        unsigned char* wh = smbuf[buf][2];
        unsigned char* wl = smbuf[buf][3];

        // ---- convert held regs -> smem bf16 hi/lo ----
#pragma unroll
        for (int i = 0; i < 4; i++) {
            const int r = lr + 16 * i;
            const uint32_t so = r * PITCH + lq * 8;
            uint32_t h0, h1, l0, l1;
            split4(xr[i], h0, h1, l0, l1);
            asm volatile("st.shared.v2.b32 [%0], {%1,%2};" :: "l"(xh + so), "r"(h0), "r"(h1));
            asm volatile("st.shared.v2.b32 [%0], {%1,%2};" :: "l"(xl + so), "r"(l0), "r"(l1));
            split4(wr[i], h0, h1, l0, l1);
            asm volatile("st.shared.v2.b32 [%0], {%1,%2};" :: "l"(wh + so), "r"(h0), "r"(h1));
            asm volatile("st.shared.v2.b32 [%0], {%1,%2};" :: "l"(wl + so), "r"(l0), "r"(l1));
        }

        // ---- prefetch next chunk while this one computes ----
        if (c + 1 < NCHUNK) {
            const int k0 = (c + 1) * KC;
#pragma unroll
            for (int i = 0; i < 4; i++) {
                xr[i] = *(const float4*)(x + (size_t)(rowbase + lr + 16 * i) * NEMB + k0 + lq * 4);
                wr[i] = *(const float4*)(W + (size_t)(lr + 16 * i) * NEMB + k0 + lq * 4);
            }
        }

        __syncthreads();

        // ---- compute: 2 k16-steps x 8 n-tiles x 3 passes ----
#pragma unroll
        for (int s = 0; s < 2; s++) {
            const int so = s * 32;                 // byte offset of k16 step
            uint32_t ah0 = lds32(xh + aoff + so);
            uint32_t ah1 = lds32(xh + aoff + so + 8 * PITCH);
            uint32_t ah2 = lds32(xh + aoff + so + 16);
            uint32_t ah3 = lds32(xh + aoff + so + 8 * PITCH + 16);
            uint32_t al0 = lds32(xl + aoff + so);
            uint32_t al1 = lds32(xl + aoff + so + 8 * PITCH);
            uint32_t al2 = lds32(xl + aoff + so + 16);
            uint32_t al3 = lds32(xl + aoff + so + 8 * PITCH + 16);
#pragma unroll
            for (int j = 0; j < 8; j++) {
                const int bo = boff_base + j * 8 * PITCH + so;
                uint32_t bh0 = lds32(wh + bo);
                uint32_t bh1 = lds32(wh + bo + 16);
                uint32_t bl0 = lds32(wl + bo);
                uint32_t bl1 = lds32(wl + bo + 16);
                mma16816(acc[j][0], acc[j][1], acc[j][2], acc[j][3],
                         ah0, ah1, ah2, ah3, bh0, bh1);
                mma16816(acc[j][0], acc[j][1], acc[j][2], acc[j][3],
                         ah0, ah1, ah2, ah3, bl0, bl1);
                mma16816(acc[j][0], acc[j][1], acc[j][2], acc[j][3],
                         al0, al1, al2, al3, bh0, bh1);
            }
        }
        __syncthreads();
    }

    // ---- epilogue: add bias, store float2 pairs ----
    const int orow = rowbase + (wid << 4) + (lid >> 2);
#pragma unroll
    for (int j = 0; j < 8; j++) {
        const int col = j * 8 + ((lid & 3) << 1);
        const float b0 = bias_s[col], b1 = bias_s[col + 1];
        float2 lo = make_float2(acc[j][0] + b0, acc[j][1] + b1);
        float2 hi = make_float2(acc[j][2] + b0, acc[j][3] + b1);
        *(float2*)(out + (size_t)orow * NH + col)       = lo;
        *(float2*)(out + (size_t)(orow + 8) * NH + col) = hi;
    }
}

extern "C" void kernel_launch(void* const* d_in, const int* in_sizes, int n_in,
                              void* d_out, int out_size)
{
    const float* x  = (const float*)d_in[0];
    const float* Wv = (const float*)d_in[5];
    const float* bv = (const float*)d_in[6];
    vproj<<<GRID, THREADS>>>(x, Wv, bv, (float*)d_out);
}

// round 4
// speedup vs baseline: 1.6044x; 1.0755x over previous
#include <cuda_runtime.h>
#include <cuda_bf16.h>
#include <cstdint>
#include <cstddef>

// out = x @ Wv^T + bv.  (Reference's softmax rows sum to 1, so its final
// einsum('btu,btj->btj', weights, v) == v + rounding; Q/K/softmax are dead.)
//
// fp32 GEMM M=8192, K=1024, N=64 via bf16-split on PORTABLE mma.sync
// (tcgen05 PTX is compute_103a-only; harness compiles via compute_103):
//   x = xh + xl, W = wh + wl (bf16); D += xh*wh + xh*wl + xl*wh (fp32 acc).
// R4: 128 CTAs x 256 threads (8 warps = 4M x 2N, warp tile m16 x n32) to fix
// the measured 1-warp/SMSP latency starvation (occ 6.3%, issue 13.6%).

#define NEMB    1024
#define NH      64
#define MT      64              // M rows per CTA
#define KC      32              // K per chunk
#define NCHUNK  (NEMB / KC)     // 32
#define THREADS 256
#define GRID    128             // 8192 / 64
#define PITCH   80              // bytes per row of 32 bf16 (conflict-free LDS)
#define TILE_B  (64 * PITCH)    // 5120 bytes per tile

__shared__ __align__(16) unsigned char smbuf[2][4][TILE_B]; // {xh, xl, wh, wl}
__shared__ float bias_s[NH];

__device__ __forceinline__ void split4(float4 f, uint32_t& uh0, uint32_t& uh1,
                                       uint32_t& ul0, uint32_t& ul1) {
    // pack k-ascending: low 16 bits = lower k
    asm("cvt.rn.bf16x2.f32 %0, %1, %2;" : "=r"(uh0) : "f"(f.y), "f"(f.x));
    asm("cvt.rn.bf16x2.f32 %0, %1, %2;" : "=r"(uh1) : "f"(f.w), "f"(f.z));
    float r0 = f.x - __uint_as_float(uh0 << 16);
    float r1 = f.y - __uint_as_float(uh0 & 0xffff0000u);
    float r2 = f.z - __uint_as_float(uh1 << 16);
    float r3 = f.w - __uint_as_float(uh1 & 0xffff0000u);
    asm("cvt.rn.bf16x2.f32 %0, %1, %2;" : "=r"(ul0) : "f"(r1), "f"(r0));
    asm("cvt.rn.bf16x2.f32 %0, %1, %2;" : "=r"(ul1) : "f"(r3), "f"(r2));
}

__device__ __forceinline__ void mma16816(float& c0, float& c1, float& c2, float& c3,
                                         uint32_t a0, uint32_t a1, uint32_t a2, uint32_t a3,
                                         uint32_t b0, uint32_t b1) {
    asm volatile(
        "mma.sync.aligned.m16n8k16.row.col.f32.bf16.bf16.f32 "
        "{%0,%1,%2,%3}, {%4,%5,%6,%7}, {%8,%9}, {%0,%1,%2,%3};"
        : "+f"(c0), "+f"(c1), "+f"(c2), "+f"(c3)
        : "r"(a0), "r"(a1), "r"(a2), "r"(a3), "r"(b0), "r"(b1));
}

__device__ __forceinline__ uint32_t lds32(const unsigned char* p) {
    uint32_t v;
    asm volatile("ld.shared.b32 %0, [%1];" : "=r"(v) : "l"(p));
    return v;
}

__global__ void __launch_bounds__(THREADS)
vproj(const float* __restrict__ x, const float* __restrict__ W,
      const float* __restrict__ bv, float* __restrict__ out)
{
    const int t   = threadIdx.x;
    const int wid = t >> 5;
    const int lid = t & 31;
    const int wm  = wid & 3;          // M slice (16 rows)
    const int wn  = wid >> 2;         // N half (32 cols)
    const int rowbase = blockIdx.x * MT;

    if (t < 16) ((float4*)bias_s)[t] = ((const float4*)bv)[t];

    // loader slots: idx = t + 256*i -> row = t>>3 + 32*i, q = t&7 (float4/row)
    const int lr = t >> 3;            // 0..31
    const int lq = t & 7;

    float acc[4][4];
#pragma unroll
    for (int j = 0; j < 4; j++)
#pragma unroll
        for (int e = 0; e < 4; e++) acc[j][e] = 0.0f;

    float4 xr[2], wr[2];
#pragma unroll
    for (int i = 0; i < 2; i++) {
        xr[i] = *(const float4*)(x + (size_t)(rowbase + lr + 32 * i) * NEMB + lq * 4);
        wr[i] = *(const float4*)(W + (size_t)(lr + 32 * i) * NEMB + lq * 4);
    }

    // per-lane fragment byte offsets
    const int fcol = (lid & 3) << 2;                        // k-pair byte offset
    const int aoff = (wm * 16 + (lid >> 2)) * PITCH + fcol; // A row
    const int boff = (lid >> 2) * PITCH + fcol;             // B row within n-tile

#pragma unroll 1
    for (int c = 0; c < NCHUNK; c++) {
        const int buf = c & 1;
        unsigned char* xh = smbuf[buf][0];
        unsigned char* xl = smbuf[buf][1];
        unsigned char* wh = smbuf[buf][2];
        unsigned char* wl = smbuf[buf][3];

        // ---- convert held regs -> smem bf16 hi/lo ----
#pragma unroll
        for (int i = 0; i < 2; i++) {
            const uint32_t so = (lr + 32 * i) * PITCH + lq * 8;
            uint32_t h0, h1, l0, l1;
            split4(xr[i], h0, h1, l0, l1);
            asm volatile("st.shared.v2.b32 [%0], {%1,%2};" :: "l"(xh + so), "r"(h0), "r"(h1));
            asm volatile("st.shared.v2.b32 [%0], {%1,%2};" :: "l"(xl + so), "r"(l0), "r"(l1));
            split4(wr[i], h0, h1, l0, l1);
            asm volatile("st.shared.v2.b32 [%0], {%1,%2};" :: "l"(wh + so), "r"(h0), "r"(h1));
            asm volatile("st.shared.v2.b32 [%0], {%1,%2};" :: "l"(wl + so), "r"(l0), "r"(l1));
        }

        // ---- prefetch next chunk while this one computes ----
        if (c + 1 < NCHUNK) {
            const int k0 = (c + 1) * KC;
#pragma unroll
            for (int i = 0; i < 2; i++) {
                xr[i] = *(const float4*)(x + (size_t)(rowbase + lr + 32 * i) * NEMB + k0 + lq * 4);
                wr[i] = *(const float4*)(W + (size_t)(lr + 32 * i) * NEMB + k0 + lq * 4);
            }
        }

        __syncthreads();

        // ---- compute: 2 k16-steps x 4 n-tiles x 3 passes ----
#pragma unroll
        for (int s = 0; s < 2; s++) {
            const int so = s * 32;
            uint32_t ah0 = lds32(xh + aoff + so);
            uint32_t ah1 = lds32(xh + aoff + so + 8 * PITCH);
            uint32_t ah2 = lds32(xh + aoff + so + 16);
            uint32_t ah3 = lds32(xh + aoff + so + 8 * PITCH + 16);
            uint32_t al0 = lds32(xl + aoff + so);
            uint32_t al1 = lds32(xl + aoff + so + 8 * PITCH);
            uint32_t al2 = lds32(xl + aoff + so + 16);
            uint32_t al3 = lds32(xl + aoff + so + 8 * PITCH + 16);
#pragma unroll
            for (int j = 0; j < 4; j++) {
                const int bo = boff + ((wn << 2) + j) * 8 * PITCH + so;
                uint32_t bh0 = lds32(wh + bo);
                uint32_t bh1 = lds32(wh + bo + 16);
                uint32_t bl0 = lds32(wl + bo);
                uint32_t bl1 = lds32(wl + bo + 16);
                mma16816(acc[j][0], acc[j][1], acc[j][2], acc[j][3],
                         ah0, ah1, ah2, ah3, bh0, bh1);
                mma16816(acc[j][0], acc[j][1], acc[j][2], acc[j][3],
                         ah0, ah1, ah2, ah3, bl0, bl1);
                mma16816(acc[j][0], acc[j][1], acc[j][2], acc[j][3],
                         al0, al1, al2, al3, bh0, bh1);
            }
        }
        __syncthreads();
    }

    // ---- epilogue: add bias, store float2 pairs ----
    const int orow = rowbase + wm * 16 + (lid >> 2);
#pragma unroll
    for (int j = 0; j < 4; j++) {
        const int col = ((wn << 2) + j) * 8 + ((lid & 3) << 1);
        const float b0 = bias_s[col], b1 = bias_s[col + 1];
        float2 lo = make_float2(acc[j][0] + b0, acc[j][1] + b1);
        float2 hi = make_float2(acc[j][2] + b0, acc[j][3] + b1);
        *(float2*)(out + (size_t)orow * NH + col)       = lo;
        *(float2*)(out + (size_t)(orow + 8) * NH + col) = hi;
    }
}

extern "C" void kernel_launch(void* const* d_in, const int* in_sizes, int n_in,
                              void* d_out, int out_size)
{
    const float* x  = (const float*)d_in[0];
    const float* Wv = (const float*)d_in[5];
    const float* bv = (const float*)d_in[6];
    vproj<<<GRID, THREADS>>>(x, Wv, bv, (float*)d_out);
}